// round 9
// baseline (speedup 1.0000x reference)
#include <cuda_runtime.h>
#include <cuda_bf16.h>

#define T_ 32
#define B_ 32
#define TB 1024
#define MAP 517
#define FLAT 132352   // 517*256
#define NACT 5
#define WCELL 66176   // 517*128 floats per cell

typedef unsigned long long u64;

// ---- packed f32x2 helpers (sm_103a FFMA2 path) ----
__device__ __forceinline__ u64 pack2(float lo, float hi) {
    u64 r;
    asm("mov.b64 %0, {%1, %2};" : "=l"(r) : "f"(lo), "f"(hi));
    return r;
}
__device__ __forceinline__ u64 fma2(u64 a, u64 b, u64 c) {
    u64 d;
    asm("fma.rn.f32x2 %0, %1, %2, %3;" : "=l"(d) : "l"(a), "l"(b), "l"(c));
    return d;
}
__device__ __forceinline__ void unpack2(u64 v, float& lo, float& hi) {
    asm("mov.b64 {%0, %1}, %2;" : "=f"(lo), "=f"(hi) : "l"(v));
}

// ---------------- scratch (device globals) ----------------
__device__ float g_Wt[FLAT * 128];      // [cell][k][j]
__device__ float g_fcwt[1024 * 512];    // [k][j]
__device__ float g_c1o[TB * 32 * 225];
__device__ float g_c2o[TB * 64 * 36];
__device__ float g_c3o[TB * 1024];
__device__ float g_h[TB * MAP];
__device__ float g_acc0[B_ * 128];
__device__ int   g_lastw[B_ * 256];
__device__ int   g_cell[TB];
__device__ int   g_code[TB];
__device__ float g_c[TB * 128];

// ======== transpose big head weights into [cell][k][j] ========
__global__ __launch_bounds__(256) void k_transW2(const float* __restrict__ pol,
                                                 const float* __restrict__ val) {
    __shared__ float tile[32][132];
    int f0 = blockIdx.x * 32;
    int tid = threadIdx.x;
    #pragma unroll
    for (int rep = 0; rep < 4; rep++) {
        int idx = tid + rep * 256;
        int j = idx >> 3, f4 = idx & 7;
        const float* src = (j < 64) ? (pol + (size_t)j * FLAT)
                                    : (val + (size_t)(j - 64) * FLAT);
        float4 v = *(const float4*)(src + f0 + f4 * 4);
        tile[f4 * 4 + 0][j] = v.x;
        tile[f4 * 4 + 1][j] = v.y;
        tile[f4 * 4 + 2][j] = v.z;
        tile[f4 * 4 + 3][j] = v.w;
    }
    __syncthreads();
    #pragma unroll
    for (int rep = 0; rep < 4; rep++) {
        int idx = tid + rep * 256;
        int fr = idx >> 5, jg = idx & 31;
        int f = f0 + fr;
        int cell = f & 255, k = f >> 8;
        float4 w = *(const float4*)&tile[fr][jg * 4];
        *(float4*)(g_Wt + (size_t)cell * WCELL + k * 128 + jg * 4) = w;
    }
}

// ---------------- transpose fc weights ----------------
__global__ void k_transFC(const float* __restrict__ fcw) {
    __shared__ float tile[32][33];
    int k = blockIdx.x * 32 + threadIdx.x;
    int j = blockIdx.y * 32 + threadIdx.y;
    tile[threadIdx.y][threadIdx.x] = fcw[j * 1024 + k];
    __syncthreads();
    int ko = blockIdx.x * 32 + threadIdx.y;
    int jo = blockIdx.y * 32 + threadIdx.x;
    g_fcwt[ko * 512 + jo] = tile[threadIdx.x][threadIdx.y];
}

// ================= conv1: (3,64,64) k8 s4 -> (32,15,15), relu (R5 body) =========
__global__ __launch_bounds__(384) void k_conv1(const float* __restrict__ img,
                                               const float* __restrict__ w,
                                               const float* __restrict__ bias) {
    extern __shared__ float sh[];
    float* simg = sh;                 // 12288
    float* swt  = sh + 12288;         // [32][193]
    int ib = blockIdx.x;
    int tid = threadIdx.x;
    const float4* ip4 = (const float4*)(img + (size_t)ib * 12288);
    for (int i = tid; i < 3072; i += 384) ((float4*)simg)[i] = ip4[i];
    for (int i = tid; i < 6144; i += 384) {
        int oc = i / 192, kk = i % 192;
        swt[oc * 193 + kk] = w[i];
    }
    __syncthreads();

    int ocg = tid & 7;
    int ntile = tid >> 3;
    bool active = (ntile < 45);
    int oy = ntile / 3, oxb = (ntile % 3) * 5;
    int ibase = active ? (oy * 256 + oxb * 4) : 0;

    u64 acc2[4][2];
    float acc1[4];
    #pragma unroll
    for (int m = 0; m < 4; m++) {
        acc2[m][0] = 0ull; acc2[m][1] = 0ull; acc1[m] = 0.f;
    }

    const float* wrow0 = swt + (ocg * 4) * 193;
    #pragma unroll
    for (int c = 0; c < 3; c++) {
        #pragma unroll
        for (int ky = 0; ky < 8; ky++) {
            int off = c * 4096 + ky * 64 + ibase;
            float row[24];
            #pragma unroll
            for (int q = 0; q < 6; q++) {
                float4 v = *(const float4*)&simg[off + q * 4];
                row[q * 4 + 0] = v.x; row[q * 4 + 1] = v.y;
                row[q * 4 + 2] = v.z; row[q * 4 + 3] = v.w;
            }
            int kb = c * 64 + ky * 8;
            #pragma unroll
            for (int kx = 0; kx < 8; kx++) {
                u64 r0 = pack2(row[kx], row[kx + 4]);
                u64 r1 = pack2(row[kx + 8], row[kx + 12]);
                float r2 = row[kx + 16];
                #pragma unroll
                for (int m = 0; m < 4; m++) {
                    float wv = wrow0[m * 193 + kb + kx];
                    u64 wp = pack2(wv, wv);
                    acc2[m][0] = fma2(wp, r0, acc2[m][0]);
                    acc2[m][1] = fma2(wp, r1, acc2[m][1]);
                    acc1[m] += wv * r2;
                }
            }
        }
    }
    if (active) {
        #pragma unroll
        for (int m = 0; m < 4; m++) {
            int oc = ocg * 4 + m;
            float bb = bias[oc];
            float a0, a1, a2, a3;
            unpack2(acc2[m][0], a0, a1);
            unpack2(acc2[m][1], a2, a3);
            float* outp = g_c1o + (size_t)ib * 7200 + oc * 225 + oy * 15 + oxb;
            outp[0] = fmaxf(a0 + bb, 0.f);
            outp[1] = fmaxf(a1 + bb, 0.f);
            outp[2] = fmaxf(a2 + bb, 0.f);
            outp[3] = fmaxf(a3 + bb, 0.f);
            outp[4] = fmaxf(acc1[m] + bb, 0.f);
        }
    }
}

// ================= conv2: (32,15,15) k4 s2 -> (64,6,6), relu ==================
// oc-paired FFMA2: weights pre-duplicated as (w[oc],w[oc+1]) u64 pairs in smem.
__global__ __launch_bounds__(384) void k_conv2(const float* __restrict__ w,
                                               const float* __restrict__ bias) {
    extern __shared__ __align__(16) char shc2[];
    float* sin_ = (float*)shc2;             // 7680 floats = 30720 B
    u64*   swt2 = (u64*)(shc2 + 30720);     // [128][33] u64 = 33792 B
    int ib4 = blockIdx.x;
    int tid = threadIdx.x;

    int ocg = tid & 15;          // 16 groups of 4 oc (= 2 oc-pairs)
    int ntile = tid >> 4;        // 4 img x 6 oy
    int img_l = ntile / 6, oy = ntile % 6;

    u64 acc2[2][6];
    #pragma unroll
    for (int p = 0; p < 2; p++)
        #pragma unroll
        for (int i = 0; i < 6; i++) acc2[p][i] = 0ull;

    for (int cb = 0; cb < 4; cb++) {
        __syncthreads();
        for (int i = tid; i < 7200; i += 384) {
            int img = i / 1800, rem = i % 1800;
            int ic = rem / 225, r2 = rem % 225;
            int y = r2 / 15, x = r2 % 15;
            sin_[img * 1920 + ic * 240 + y * 16 + x] =
                g_c1o[(size_t)ib4 * 28800 + img * 7200 + cb * 1800 + rem];
        }
        // duplicated weight pairs: swt2[kk][pr] = (w[2pr][kk], w[2pr+1][kk])
        for (int i = tid; i < 4096; i += 384) {
            int kk = i >> 5, pr = i & 31;
            int oc0 = pr * 2;
            float v0 = w[oc0 * 512 + cb * 128 + kk];
            float v1 = w[(oc0 + 1) * 512 + cb * 128 + kk];
            swt2[kk * 33 + pr] = pack2(v0, v1);
        }
        __syncthreads();
        int base_in = img_l * 1920;
        #pragma unroll
        for (int icl = 0; icl < 8; icl++) {
            int pbase = base_in + icl * 240;
            #pragma unroll
            for (int ky = 0; ky < 4; ky++) {
                int off = pbase + (oy * 2 + ky) * 16;
                u64 rr[14];
                #pragma unroll
                for (int q = 0; q < 3; q++) {
                    float4 v = *(const float4*)&sin_[off + q * 4];
                    rr[q * 4 + 0] = pack2(v.x, v.x);
                    rr[q * 4 + 1] = pack2(v.y, v.y);
                    rr[q * 4 + 2] = pack2(v.z, v.z);
                    rr[q * 4 + 3] = pack2(v.w, v.w);
                }
                {
                    float a = sin_[off + 12], b2 = sin_[off + 13];
                    rr[12] = pack2(a, a);
                    rr[13] = pack2(b2, b2);
                }
                int kb = icl * 16 + ky * 4;
                #pragma unroll
                for (int kx = 0; kx < 4; kx++) {
                    const u64* wk = swt2 + (kb + kx) * 33 + 2 * ocg;
                    u64 wp0 = wk[0];
                    u64 wp1 = wk[1];
                    #pragma unroll
                    for (int i = 0; i < 6; i++) {
                        acc2[0][i] = fma2(wp0, rr[kx + 2 * i], acc2[0][i]);
                        acc2[1][i] = fma2(wp1, rr[kx + 2 * i], acc2[1][i]);
                    }
                }
            }
        }
    }
    int ib = ib4 * 4 + img_l;
    #pragma unroll
    for (int p = 0; p < 2; p++) {
        int oc_lo = ocg * 4 + p * 2;
        float b0 = bias[oc_lo], b1 = bias[oc_lo + 1];
        float* o0 = g_c2o + (size_t)ib * 2304 + oc_lo * 36 + oy * 6;
        float* o1 = o0 + 36;
        #pragma unroll
        for (int i = 0; i < 6; i++) {
            float lo, hi;
            unpack2(acc2[p][i], lo, hi);
            o0[i] = fmaxf(lo + b0, 0.f);
            o1[i] = fmaxf(hi + b1, 0.f);
        }
    }
}

// ================= conv3: (64,6,6) k3 s1 -> (64,4,4), relu ==================
// oc-paired FFMA2 with duplicated weight pairs in smem.
__global__ __launch_bounds__(256) void k_conv3(const float* __restrict__ w,
                                               const float* __restrict__ bias) {
    extern __shared__ __align__(16) char shc3[];
    float* sin_ = (float*)shc3;             // 3072 floats = 12288 B
    u64*   swt2 = (u64*)(shc3 + 12288);     // [144][33] u64 = 38016 B
    int ib4 = blockIdx.x;
    int tid = threadIdx.x;

    int ocg = tid & 15;          // 16 groups of 4 oc (= 2 oc-pairs)
    int ntile = tid >> 4;        // 4 img x 4 oy
    int img_l = ntile >> 2, oy = ntile & 3;

    u64 acc2[2][4];
    #pragma unroll
    for (int p = 0; p < 2; p++)
        #pragma unroll
        for (int i = 0; i < 4; i++) acc2[p][i] = 0ull;

    for (int cb = 0; cb < 4; cb++) {
        __syncthreads();
        for (int i = tid; i < 2304; i += 256) {
            int img = i / 576, rem = i % 576;
            int ic = rem / 36, r2 = rem % 36;
            int y = r2 / 6, x = r2 % 6;
            sin_[img * 768 + ic * 48 + y * 8 + x] =
                g_c2o[(size_t)ib4 * 9216 + img * 2304 + cb * 576 + rem];
        }
        for (int i = tid; i < 4608; i += 256) {
            int kk = i >> 5, pr = i & 31;
            int oc0 = pr * 2;
            float v0 = w[oc0 * 576 + cb * 144 + kk];
            float v1 = w[(oc0 + 1) * 576 + cb * 144 + kk];
            swt2[kk * 33 + pr] = pack2(v0, v1);
        }
        __syncthreads();
        int base_in = img_l * 768;
        #pragma unroll
        for (int icl = 0; icl < 16; icl++) {
            int pbase = base_in + icl * 48;
            #pragma unroll
            for (int ky = 0; ky < 3; ky++) {
                int off = pbase + (oy + ky) * 8;
                u64 rr[6];
                float4 v = *(const float4*)&sin_[off];
                rr[0] = pack2(v.x, v.x);
                rr[1] = pack2(v.y, v.y);
                rr[2] = pack2(v.z, v.z);
                rr[3] = pack2(v.w, v.w);
                {
                    float a = sin_[off + 4], b2 = sin_[off + 5];
                    rr[4] = pack2(a, a);
                    rr[5] = pack2(b2, b2);
                }
                int kb = icl * 9 + ky * 3;
                #pragma unroll
                for (int kx = 0; kx < 3; kx++) {
                    const u64* wk = swt2 + (kb + kx) * 33 + 2 * ocg;
                    u64 wp0 = wk[0];
                    u64 wp1 = wk[1];
                    #pragma unroll
                    for (int i = 0; i < 4; i++) {
                        acc2[0][i] = fma2(wp0, rr[kx + i], acc2[0][i]);
                        acc2[1][i] = fma2(wp1, rr[kx + i], acc2[1][i]);
                    }
                }
            }
        }
    }
    int ib = ib4 * 4 + img_l;
    #pragma unroll
    for (int p = 0; p < 2; p++) {
        int oc_lo = ocg * 4 + p * 2;
        float b0 = bias[oc_lo], b1 = bias[oc_lo + 1];
        float* o0 = g_c3o + (size_t)ib * 1024 + oc_lo * 16 + oy * 4;
        float* o1 = o0 + 16;
        #pragma unroll
        for (int i = 0; i < 4; i++) {
            float lo, hi;
            unpack2(acc2[p][i], lo, hi);
            o0[i] = fmaxf(lo + b0, 0.f);
            o1[i] = fmaxf(hi + b1, 0.f);
        }
    }
}

// ================= fc: SGEMM 1024x512x1024 -> g_h (+relu) ==========
__global__ __launch_bounds__(256) void k_fc2(const float* __restrict__ bias) {
    __shared__ __align__(16) float Xs[32][72];   // [kk][img]
    __shared__ __align__(16) float Ws[32][64];   // [kk][oc]
    int i0 = blockIdx.x * 64;
    int j0 = blockIdx.y * 64;
    int tid = threadIdx.x;
    int im_g = tid & 15, oc_g = tid >> 4;

    u64 acc2[4][2];
    #pragma unroll
    for (int m = 0; m < 4; m++) { acc2[m][0] = 0ull; acc2[m][1] = 0ull; }

    for (int k0 = 0; k0 < 1024; k0 += 32) {
        __syncthreads();
        #pragma unroll
        for (int r = 0; r < 2; r++) {
            int idx = tid + 256 * r;
            int im = idx & 63, kq = idx >> 6;
            float4 v = *(const float4*)&g_c3o[(size_t)(i0 + im) * 1024 + k0 + kq * 4];
            Xs[kq * 4 + 0][im] = v.x;
            Xs[kq * 4 + 1][im] = v.y;
            Xs[kq * 4 + 2][im] = v.z;
            Xs[kq * 4 + 3][im] = v.w;
        }
        #pragma unroll
        for (int r = 0; r < 2; r++) {
            int idx = tid + 256 * r;
            int kk = idx >> 4, oc4 = idx & 15;
            float4 v = *(const float4*)&g_fcwt[(size_t)(k0 + kk) * 512 + j0 + oc4 * 4];
            *(float4*)&Ws[kk][oc4 * 4] = v;
        }
        __syncthreads();
        #pragma unroll
        for (int kk = 0; kk < 32; kk++) {
            float4 wv = *(const float4*)&Ws[kk][oc_g * 4];
            float4 xv = *(const float4*)&Xs[kk][im_g * 4];
            u64 wp0 = pack2(wv.x, wv.y);
            u64 wp1 = pack2(wv.z, wv.w);
            u64 x0 = pack2(xv.x, xv.x);
            u64 x1 = pack2(xv.y, xv.y);
            u64 x2 = pack2(xv.z, xv.z);
            u64 x3 = pack2(xv.w, xv.w);
            acc2[0][0] = fma2(x0, wp0, acc2[0][0]);
            acc2[0][1] = fma2(x0, wp1, acc2[0][1]);
            acc2[1][0] = fma2(x1, wp0, acc2[1][0]);
            acc2[1][1] = fma2(x1, wp1, acc2[1][1]);
            acc2[2][0] = fma2(x2, wp0, acc2[2][0]);
            acc2[2][1] = fma2(x2, wp1, acc2[2][1]);
            acc2[3][0] = fma2(x3, wp0, acc2[3][0]);
            acc2[3][1] = fma2(x3, wp1, acc2[3][1]);
        }
    }
    #pragma unroll
    for (int m = 0; m < 4; m++) {
        int img = i0 + im_g * 4 + m;
        float a0, a1, a2, a3;
        unpack2(acc2[m][0], a0, a1);
        unpack2(acc2[m][1], a2, a3);
        int oc = j0 + oc_g * 4;
        g_h[(size_t)img * MAP + oc + 0] = fmaxf(a0 + bias[oc + 0], 0.f);
        g_h[(size_t)img * MAP + oc + 1] = fmaxf(a1 + bias[oc + 1], 0.f);
        g_h[(size_t)img * MAP + oc + 2] = fmaxf(a2 + bias[oc + 2], 0.f);
        g_h[(size_t)img * MAP + oc + 3] = fmaxf(a3 + bias[oc + 3], 0.f);
    }
}

// ---------------- onehot tail of g_h ----------------
__global__ void k_onehot(const int* __restrict__ lastact) {
    int i = blockIdx.x * 256 + threadIdx.x;
    if (i < TB * NACT) {
        int ib = i / NACT, a = i % NACT;
        g_h[(size_t)ib * MAP + 512 + a] = (lastact[ib] == a) ? 1.f : 0.f;
    }
}

// ======== acc0[j][b] = sum_f W[j][f]*s0[b][f] ========
__global__ __launch_bounds__(256) void k_acc0(const float* __restrict__ pol,
                                              const float* __restrict__ val,
                                              const float* __restrict__ s0) {
    __shared__ __align__(16) float Wt2[64][132];
    __shared__ __align__(16) float Ss[64][36];
    int kb0 = blockIdx.x * 256;
    int tid = threadIdx.x;
    int jg = tid >> 3;
    int bg = tid & 7;

    float acc[4][4];
    #pragma unroll
    for (int m = 0; m < 4; m++)
        #pragma unroll
        for (int n = 0; n < 4; n++) acc[m][n] = 0.f;

    for (int sub = 0; sub < 4; sub++) {
        int kbase = kb0 + sub * 64;
        __syncthreads();
        for (int i = tid; i < 8192; i += 256) {
            int kk = i & 63, j = i >> 6;
            const float* src = (j < 64) ? (pol + (size_t)j * FLAT)
                                        : (val + (size_t)(j - 64) * FLAT);
            Wt2[kk][j] = src[kbase + kk];
        }
        for (int i = tid; i < 2048; i += 256) {
            int kk = i & 63, b = i >> 6;
            Ss[kk][b] = s0[(size_t)b * FLAT + kbase + kk];
        }
        __syncthreads();
        #pragma unroll
        for (int kk = 0; kk < 64; kk++) {
            float4 wv = *(const float4*)&Wt2[kk][jg * 4];
            float4 sv = *(const float4*)&Ss[kk][bg * 4];
            acc[0][0] += wv.x * sv.x; acc[0][1] += wv.x * sv.y;
            acc[0][2] += wv.x * sv.z; acc[0][3] += wv.x * sv.w;
            acc[1][0] += wv.y * sv.x; acc[1][1] += wv.y * sv.y;
            acc[1][2] += wv.y * sv.z; acc[1][3] += wv.y * sv.w;
            acc[2][0] += wv.z * sv.x; acc[2][1] += wv.z * sv.y;
            acc[2][2] += wv.z * sv.z; acc[2][3] += wv.z * sv.w;
            acc[3][0] += wv.w * sv.x; acc[3][1] += wv.w * sv.y;
            acc[3][2] += wv.w * sv.z; acc[3][3] += wv.w * sv.w;
        }
    }
    #pragma unroll
    for (int m = 0; m < 4; m++)
        #pragma unroll
        for (int n = 0; n < 4; n++)
            atomicAdd(&g_acc0[(bg * 4 + n) * 128 + jg * 4 + m], acc[m][n]);
}

// ======== pass 1: last-writer scan, one block per env, also zeroes acc0 ========
__global__ __launch_bounds__(32) void k_codes(const int* __restrict__ pos,
                                              const float* __restrict__ done) {
    __shared__ int lw[256];
    __shared__ int cells[T_];
    __shared__ float dns[T_];
    int b = blockIdx.x;
    int tid = threadIdx.x;
    #pragma unroll
    for (int q = 0; q < 4; q++) g_acc0[b * 128 + tid + q * 32] = 0.f;
    {
        int r = tid * B_ + b;
        dns[tid] = done[r];
        cells[tid] = pos[r * 2] * 16 + pos[r * 2 + 1];
    }
    for (int c = tid; c < 256; c += 32) lw[c] = -2;
    __syncwarp();
    for (int t = 0; t < T_; t++) {
        if (dns[t] != 0.0f) {
            for (int c = tid; c < 256; c += 32) lw[c] = -1;
            __syncwarp();
        }
        if (tid == 0) {
            int r = t * B_ + b;
            int cell = cells[t];
            g_cell[r] = cell;
            g_code[r] = lw[cell];
            lw[cell] = t;
        }
        __syncwarp();
    }
    for (int c = tid; c < 256; c += 32) g_lastw[b * 256 + c] = lw[c];
}

// ======== pass 2: parallel per-(t,b) contribution dot products ========
__global__ __launch_bounds__(256) void k_dots(const float* __restrict__ s0) {
    __shared__ float delta[520];
    __shared__ float psum[8 * 128];
    int r = blockIdx.x;
    int b = r & 31;
    int tid = threadIdx.x;
    int cell = g_cell[r];
    int code = g_code[r];
    const float* hrow = g_h + (size_t)r * MAP;
    for (int k = tid; k < MAP; k += 256) {
        float old = 0.f;
        if (code >= 0)       old = g_h[(size_t)(code * B_ + b) * MAP + k];
        else if (code == -2) old = s0[(size_t)b * FLAT + k * 256 + cell];
        delta[k] = hrow[k] - old;
    }
    __syncthreads();
    int j4 = tid & 31;
    int kq = tid >> 5;
    const float* wb = g_Wt + (size_t)cell * WCELL + j4 * 4;
    float4 a = make_float4(0.f, 0.f, 0.f, 0.f);
    for (int k = kq; k < MAP; k += 8) {
        float4 w = *(const float4*)(wb + k * 128);
        float d = delta[k];
        a.x += w.x * d; a.y += w.y * d; a.z += w.z * d; a.w += w.w * d;
    }
    psum[kq * 128 + j4 * 4 + 0] = a.x;
    psum[kq * 128 + j4 * 4 + 1] = a.y;
    psum[kq * 128 + j4 * 4 + 2] = a.z;
    psum[kq * 128 + j4 * 4 + 3] = a.w;
    __syncthreads();
    if (tid < 128) {
        float s = 0.f;
        #pragma unroll
        for (int q = 0; q < 8; q++) s += psum[q * 128 + tid];
        g_c[(size_t)r * 128 + tid] = s;
    }
}

// ======== pass 3: prefix accumulate + tanh + head GEMVs ========
__global__ __launch_bounds__(128) void k_scanfin(const float* __restrict__ done,
                                                 const float* __restrict__ pb1,
                                                 const float* __restrict__ vb1,
                                                 const float* __restrict__ pw2,
                                                 const float* __restrict__ pb2,
                                                 const float* __restrict__ vw2,
                                                 const float* __restrict__ vb2,
                                                 float* __restrict__ logits,
                                                 float* __restrict__ vout) {
    __shared__ float th[128];
    int b = blockIdx.x;
    int tid = threadIdx.x;
    float accv = g_acc0[b * 128 + tid];
    float bb = (tid < 64) ? pb1[tid] : vb1[tid - 64];
    for (int t = 0; t < T_; t++) {
        int r = t * B_ + b;
        float dn = done[r];
        if (dn != 0.0f) accv = 0.f;
        accv += g_c[(size_t)r * 128 + tid];
        th[tid] = tanhf(accv + bb);
        __syncthreads();
        if (tid < NACT) {
            float s = pb2[tid];
            #pragma unroll
            for (int q = 0; q < 64; q++) s += th[q] * pw2[tid * 64 + q];
            logits[r * NACT + tid] = s;
        } else if (tid == 8) {
            float s = vb2[0];
            #pragma unroll
            for (int q = 0; q < 64; q++) s += th[64 + q] * vw2[q];
            vout[r] = s;
        }
        __syncthreads();
    }
}

// ---------------- reconstruct final_state ----------------
__global__ __launch_bounds__(256) void k_final(const float* __restrict__ s0,
                                               float* __restrict__ out) {
    int b = blockIdx.y;
    int f = blockIdx.x * 256 + threadIdx.x;
    int cell = f & 255, k = f >> 8;
    int code = g_lastw[b * 256 + cell];
    float v;
    if (code >= 0)       v = g_h[(size_t)(code * B_ + b) * MAP + k];
    else if (code == -2) v = s0[(size_t)b * FLAT + f];
    else                 v = 0.f;
    out[(size_t)b * FLAT + f] = v;
}

// ---------------- host ----------------
extern "C" void kernel_launch(void* const* d_in, const int* in_sizes, int n_in,
                              void* d_out, int out_size) {
    const float* image  = (const float*)d_in[0];
    const int*   lact   = (const int*)  d_in[1];
    const int*   pos    = (const int*)  d_in[2];
    const float* done   = (const float*)d_in[3];
    const float* state0 = (const float*)d_in[4];
    const float* c1w = (const float*)d_in[5];
    const float* c1b = (const float*)d_in[6];
    const float* c2w = (const float*)d_in[7];
    const float* c2b = (const float*)d_in[8];
    const float* c3w = (const float*)d_in[9];
    const float* c3b = (const float*)d_in[10];
    const float* fcw = (const float*)d_in[11];
    const float* fcb = (const float*)d_in[12];
    const float* pw1 = (const float*)d_in[13];
    const float* pb1 = (const float*)d_in[14];
    const float* pw2 = (const float*)d_in[15];
    const float* pb2 = (const float*)d_in[16];
    const float* vw1 = (const float*)d_in[17];
    const float* vb1 = (const float*)d_in[18];
    const float* vw2 = (const float*)d_in[19];
    const float* vb2 = (const float*)d_in[20];

    float* out_logits = (float*)d_out;
    float* out_v      = (float*)d_out + TB * NACT;
    float* out_state  = (float*)d_out + TB * NACT + TB;

    static cudaStream_t sA = nullptr, sB = nullptr;
    static cudaEvent_t ev0, evA, evB, evH, evFin;
    static int init_done = 0;
    if (!init_done) {
        cudaStreamCreateWithFlags(&sA, cudaStreamNonBlocking);
        cudaStreamCreateWithFlags(&sB, cudaStreamNonBlocking);
        cudaEventCreateWithFlags(&ev0,  cudaEventDisableTiming);
        cudaEventCreateWithFlags(&evA,  cudaEventDisableTiming);
        cudaEventCreateWithFlags(&evB,  cudaEventDisableTiming);
        cudaEventCreateWithFlags(&evH,  cudaEventDisableTiming);
        cudaEventCreateWithFlags(&evFin, cudaEventDisableTiming);
        cudaFuncSetAttribute(k_conv1, cudaFuncAttributeMaxDynamicSharedMemorySize, 73856);
        cudaFuncSetAttribute(k_conv2, cudaFuncAttributeMaxDynamicSharedMemorySize, 64512);
        cudaFuncSetAttribute(k_conv3, cudaFuncAttributeMaxDynamicSharedMemorySize, 50304);
        init_done = 1;
    }

    // fork side streams off the capture (default) stream (R7 schedule)
    cudaEventRecord(ev0, 0);
    cudaStreamWaitEvent(sA, ev0, 0);
    cudaStreamWaitEvent(sB, ev0, 0);

    // stream A: codes(+zero) + acc0 + onehot (independent of conv path)
    k_codes<<<B_, 32, 0, sA>>>(pos, done);
    k_acc0 <<<517, 256, 0, sA>>>(pw1, vw1, state0);
    k_onehot<<<(TB * NACT + 255) / 256, 256, 0, sA>>>(lact);
    cudaEventRecord(evA, sA);

    // stream B: big weight transpose + fc transpose
    k_transW2<<<FLAT / 32, 256, 0, sB>>>(pw1, vw1);
    k_transFC<<<dim3(32, 16), dim3(32, 32), 0, sB>>>(fcw);
    cudaEventRecord(evB, sB);

    // main stream: CNN feature path
    k_conv1<<<TB, 384, 73856>>>(image, c1w, c1b);
    k_conv2<<<TB / 4, 384, 64512>>>(c2w, c2b);
    k_conv3<<<TB / 4, 256, 50304>>>(c3w, c3b);

    // fc needs transFC
    cudaStreamWaitEvent(0, evB, 0);
    k_fc2<<<dim3(16, 8), 256>>>(fcb);
    cudaEventRecord(evH, 0);

    // final_state on stream B (overlaps dots/scanfin)
    cudaStreamWaitEvent(sB, evH, 0);
    cudaStreamWaitEvent(sB, evA, 0);
    k_final<<<dim3(FLAT / 256, B_), 256, 0, sB>>>(state0, out_state);
    cudaEventRecord(evFin, sB);

    // main stream: dots + sequential finish
    cudaStreamWaitEvent(0, evA, 0);
    k_dots   <<<TB, 256>>>(state0);
    k_scanfin<<<B_, 128>>>(done, pb1, vb1, pw2, pb2, vw2, vb2, out_logits, out_v);

    // join stream B back before capture end
    cudaStreamWaitEvent(0, evFin, 0);

    (void)in_sizes; (void)n_in; (void)out_size;
}

// round 10
// speedup vs baseline: 1.1982x; 1.1982x over previous
#include <cuda_runtime.h>
#include <cuda_bf16.h>

#define T_ 32
#define B_ 32
#define TB 1024
#define MAP 517
#define FLAT 132352   // 517*256
#define NACT 5
#define WCELL 66176   // 517*128 floats per cell

typedef unsigned long long u64;

// ---- packed f32x2 helpers (sm_103a FFMA2 path) ----
__device__ __forceinline__ u64 pack2(float lo, float hi) {
    u64 r;
    asm("mov.b64 %0, {%1, %2};" : "=l"(r) : "f"(lo), "f"(hi));
    return r;
}
__device__ __forceinline__ u64 fma2(u64 a, u64 b, u64 c) {
    u64 d;
    asm("fma.rn.f32x2 %0, %1, %2, %3;" : "=l"(d) : "l"(a), "l"(b), "l"(c));
    return d;
}
__device__ __forceinline__ void unpack2(u64 v, float& lo, float& hi) {
    asm("mov.b64 {%0, %1}, %2;" : "=f"(lo), "=f"(hi) : "l"(v));
}

// ---------------- scratch (device globals) ----------------
__device__ float g_Wt[FLAT * 128];      // [cell][k][j]
__device__ float g_fcwt[1024 * 512];    // [k][j]
__device__ float g_c1o[TB * 32 * 225];
__device__ float g_c2o[TB * 64 * 36];
__device__ float g_c3o[TB * 1024];
__device__ float g_h[TB * MAP];
__device__ float g_acc0[B_ * 128];
__device__ int   g_lastw[B_ * 256];
__device__ int   g_cell[TB];
__device__ int   g_code[TB];
__device__ float g_c[TB * 128];
__device__ float g_th[TB * 128];        // tanh(hidden@W1+b1) per (t,b)

// ======== transpose big head weights into [cell][k][j] ========
__global__ __launch_bounds__(256) void k_transW2(const float* __restrict__ pol,
                                                 const float* __restrict__ val) {
    __shared__ float tile[32][132];
    int f0 = blockIdx.x * 32;
    int tid = threadIdx.x;
    #pragma unroll
    for (int rep = 0; rep < 4; rep++) {
        int idx = tid + rep * 256;
        int j = idx >> 3, f4 = idx & 7;
        const float* src = (j < 64) ? (pol + (size_t)j * FLAT)
                                    : (val + (size_t)(j - 64) * FLAT);
        float4 v = *(const float4*)(src + f0 + f4 * 4);
        tile[f4 * 4 + 0][j] = v.x;
        tile[f4 * 4 + 1][j] = v.y;
        tile[f4 * 4 + 2][j] = v.z;
        tile[f4 * 4 + 3][j] = v.w;
    }
    __syncthreads();
    #pragma unroll
    for (int rep = 0; rep < 4; rep++) {
        int idx = tid + rep * 256;
        int fr = idx >> 5, jg = idx & 31;
        int f = f0 + fr;
        int cell = f & 255, k = f >> 8;
        float4 w = *(const float4*)&tile[fr][jg * 4];
        *(float4*)(g_Wt + (size_t)cell * WCELL + k * 128 + jg * 4) = w;
    }
}

// ---------------- transpose fc weights ----------------
__global__ void k_transFC(const float* __restrict__ fcw) {
    __shared__ float tile[32][33];
    int k = blockIdx.x * 32 + threadIdx.x;
    int j = blockIdx.y * 32 + threadIdx.y;
    tile[threadIdx.y][threadIdx.x] = fcw[j * 1024 + k];
    __syncthreads();
    int ko = blockIdx.x * 32 + threadIdx.y;
    int jo = blockIdx.y * 32 + threadIdx.x;
    g_fcwt[ko * 512 + jo] = tile[threadIdx.x][threadIdx.y];
}

// ================= conv1: (3,64,64) k8 s4 -> (32,15,15), relu (R5 body) =========
__global__ __launch_bounds__(384) void k_conv1(const float* __restrict__ img,
                                               const float* __restrict__ w,
                                               const float* __restrict__ bias) {
    extern __shared__ float sh[];
    float* simg = sh;                 // 12288
    float* swt  = sh + 12288;         // [32][193]
    int ib = blockIdx.x;
    int tid = threadIdx.x;
    const float4* ip4 = (const float4*)(img + (size_t)ib * 12288);
    for (int i = tid; i < 3072; i += 384) ((float4*)simg)[i] = ip4[i];
    for (int i = tid; i < 6144; i += 384) {
        int oc = i / 192, kk = i % 192;
        swt[oc * 193 + kk] = w[i];
    }
    __syncthreads();

    int ocg = tid & 7;
    int ntile = tid >> 3;
    bool active = (ntile < 45);
    int oy = ntile / 3, oxb = (ntile % 3) * 5;
    int ibase = active ? (oy * 256 + oxb * 4) : 0;

    u64 acc2[4][2];
    float acc1[4];
    #pragma unroll
    for (int m = 0; m < 4; m++) {
        acc2[m][0] = 0ull; acc2[m][1] = 0ull; acc1[m] = 0.f;
    }

    const float* wrow0 = swt + (ocg * 4) * 193;
    #pragma unroll
    for (int c = 0; c < 3; c++) {
        #pragma unroll
        for (int ky = 0; ky < 8; ky++) {
            int off = c * 4096 + ky * 64 + ibase;
            float row[24];
            #pragma unroll
            for (int q = 0; q < 6; q++) {
                float4 v = *(const float4*)&simg[off + q * 4];
                row[q * 4 + 0] = v.x; row[q * 4 + 1] = v.y;
                row[q * 4 + 2] = v.z; row[q * 4 + 3] = v.w;
            }
            int kb = c * 64 + ky * 8;
            #pragma unroll
            for (int kx = 0; kx < 8; kx++) {
                u64 r0 = pack2(row[kx], row[kx + 4]);
                u64 r1 = pack2(row[kx + 8], row[kx + 12]);
                float r2 = row[kx + 16];
                #pragma unroll
                for (int m = 0; m < 4; m++) {
                    float wv = wrow0[m * 193 + kb + kx];
                    u64 wp = pack2(wv, wv);
                    acc2[m][0] = fma2(wp, r0, acc2[m][0]);
                    acc2[m][1] = fma2(wp, r1, acc2[m][1]);
                    acc1[m] += wv * r2;
                }
            }
        }
    }
    if (active) {
        #pragma unroll
        for (int m = 0; m < 4; m++) {
            int oc = ocg * 4 + m;
            float bb = bias[oc];
            float a0, a1, a2, a3;
            unpack2(acc2[m][0], a0, a1);
            unpack2(acc2[m][1], a2, a3);
            float* outp = g_c1o + (size_t)ib * 7200 + oc * 225 + oy * 15 + oxb;
            outp[0] = fmaxf(a0 + bb, 0.f);
            outp[1] = fmaxf(a1 + bb, 0.f);
            outp[2] = fmaxf(a2 + bb, 0.f);
            outp[3] = fmaxf(a3 + bb, 0.f);
            outp[4] = fmaxf(acc1[m] + bb, 0.f);
        }
    }
}

// ================= conv2: (32,15,15) k4 s2 -> (64,6,6), relu (R5 body) ==========
__global__ __launch_bounds__(384) void k_conv2(const float* __restrict__ w,
                                               const float* __restrict__ bias) {
    extern __shared__ float sh[];
    float* sin_ = sh;            // 4 img * 8 ic * 240 = 7680
    float* swt  = sh + 7680;     // [64][129] = 8256
    int ib4 = blockIdx.x;
    int tid = threadIdx.x;

    int ocg = tid & 15;
    int ntile = tid >> 4;
    int img_l = ntile / 6, oy = ntile % 6;

    u64 acc2[4][3];
    #pragma unroll
    for (int m = 0; m < 4; m++)
        #pragma unroll
        for (int p = 0; p < 3; p++) acc2[m][p] = 0ull;

    for (int cb = 0; cb < 4; cb++) {
        __syncthreads();
        for (int i = tid; i < 7200; i += 384) {
            int img = i / 1800, rem = i % 1800;
            int ic = rem / 225, r2 = rem % 225;
            int y = r2 / 15, x = r2 % 15;
            sin_[img * 1920 + ic * 240 + y * 16 + x] =
                g_c1o[(size_t)ib4 * 28800 + img * 7200 + cb * 1800 + rem];
        }
        for (int i = tid; i < 8192; i += 384) {
            int oc = i >> 7, kk = i & 127;
            swt[oc * 129 + kk] = w[oc * 512 + cb * 128 + kk];
        }
        __syncthreads();
        const float* wrow0 = swt + (ocg * 4) * 129;
        int base_in = img_l * 1920;
        #pragma unroll
        for (int icl = 0; icl < 8; icl++) {
            int pbase = base_in + icl * 240;
            #pragma unroll
            for (int ky = 0; ky < 4; ky++) {
                int off = pbase + (oy * 2 + ky) * 16;
                float row[14];
                #pragma unroll
                for (int q = 0; q < 3; q++) {
                    float4 v = *(const float4*)&sin_[off + q * 4];
                    row[q * 4 + 0] = v.x; row[q * 4 + 1] = v.y;
                    row[q * 4 + 2] = v.z; row[q * 4 + 3] = v.w;
                }
                row[12] = sin_[off + 12];
                row[13] = sin_[off + 13];
                int kb = icl * 16 + ky * 4;
                #pragma unroll
                for (int kx = 0; kx < 4; kx++) {
                    u64 r0 = pack2(row[kx], row[kx + 2]);
                    u64 r1 = pack2(row[kx + 4], row[kx + 6]);
                    u64 r2 = pack2(row[kx + 8], row[kx + 10]);
                    #pragma unroll
                    for (int m = 0; m < 4; m++) {
                        float wv = wrow0[m * 129 + kb + kx];
                        u64 wp = pack2(wv, wv);
                        acc2[m][0] = fma2(wp, r0, acc2[m][0]);
                        acc2[m][1] = fma2(wp, r1, acc2[m][1]);
                        acc2[m][2] = fma2(wp, r2, acc2[m][2]);
                    }
                }
            }
        }
    }
    int ib = ib4 * 4 + img_l;
    #pragma unroll
    for (int m = 0; m < 4; m++) {
        int oc = ocg * 4 + m;
        float bb = bias[oc];
        float* outp = g_c2o + (size_t)ib * 2304 + oc * 36 + oy * 6;
        #pragma unroll
        for (int p = 0; p < 3; p++) {
            float lo, hi;
            unpack2(acc2[m][p], lo, hi);
            outp[p * 2 + 0] = fmaxf(lo + bb, 0.f);
            outp[p * 2 + 1] = fmaxf(hi + bb, 0.f);
        }
    }
}

// ================= conv3: (64,6,6) k3 s1 -> (64,4,4), relu (R5 body) ============
__global__ __launch_bounds__(256) void k_conv3(const float* __restrict__ w,
                                               const float* __restrict__ bias) {
    extern __shared__ float sh[];
    float* sin_ = sh;            // 4 img * 16 ic * 48 = 3072
    float* swt  = sh + 3072;     // [64][145] = 9280
    int ib4 = blockIdx.x;
    int tid = threadIdx.x;

    int ocg = tid & 15;
    int ntile = tid >> 4;
    int img_l = ntile >> 2, oy = ntile & 3;

    u64 acc2[4][2];
    #pragma unroll
    for (int m = 0; m < 4; m++) { acc2[m][0] = 0ull; acc2[m][1] = 0ull; }

    for (int cb = 0; cb < 4; cb++) {
        __syncthreads();
        for (int i = tid; i < 2304; i += 256) {
            int img = i / 576, rem = i % 576;
            int ic = rem / 36, r2 = rem % 36;
            int y = r2 / 6, x = r2 % 6;
            sin_[img * 768 + ic * 48 + y * 8 + x] =
                g_c2o[(size_t)ib4 * 9216 + img * 2304 + cb * 576 + rem];
        }
        for (int i = tid; i < 9216; i += 256) {
            int oc = i / 144, kk = i % 144;
            swt[oc * 145 + kk] = w[oc * 576 + cb * 144 + kk];
        }
        __syncthreads();
        const float* wrow0 = swt + (ocg * 4) * 145;
        int base_in = img_l * 768;
        #pragma unroll
        for (int icl = 0; icl < 16; icl++) {
            int pbase = base_in + icl * 48;
            #pragma unroll
            for (int ky = 0; ky < 3; ky++) {
                int off = pbase + (oy + ky) * 8;
                float row[6];
                float4 v = *(const float4*)&sin_[off];
                row[0] = v.x; row[1] = v.y; row[2] = v.z; row[3] = v.w;
                row[4] = sin_[off + 4];
                row[5] = sin_[off + 5];
                int kb = icl * 9 + ky * 3;
                #pragma unroll
                for (int kx = 0; kx < 3; kx++) {
                    u64 r0 = pack2(row[kx], row[kx + 1]);
                    u64 r1 = pack2(row[kx + 2], row[kx + 3]);
                    #pragma unroll
                    for (int m = 0; m < 4; m++) {
                        float wv = wrow0[m * 145 + kb + kx];
                        u64 wp = pack2(wv, wv);
                        acc2[m][0] = fma2(wp, r0, acc2[m][0]);
                        acc2[m][1] = fma2(wp, r1, acc2[m][1]);
                    }
                }
            }
        }
    }
    int ib = ib4 * 4 + img_l;
    #pragma unroll
    for (int m = 0; m < 4; m++) {
        int oc = ocg * 4 + m;
        float bb = bias[oc];
        float* outp = g_c3o + (size_t)ib * 1024 + oc * 16 + oy * 4;
        float a0, a1, a2, a3;
        unpack2(acc2[m][0], a0, a1);
        unpack2(acc2[m][1], a2, a3);
        outp[0] = fmaxf(a0 + bb, 0.f);
        outp[1] = fmaxf(a1 + bb, 0.f);
        outp[2] = fmaxf(a2 + bb, 0.f);
        outp[3] = fmaxf(a3 + bb, 0.f);
    }
}

// ================= fc: SGEMM 1024x512x1024 -> g_h (+relu) ==========
__global__ __launch_bounds__(256) void k_fc2(const float* __restrict__ bias) {
    __shared__ __align__(16) float Xs[32][72];   // [kk][img]
    __shared__ __align__(16) float Ws[32][64];   // [kk][oc]
    int i0 = blockIdx.x * 64;
    int j0 = blockIdx.y * 64;
    int tid = threadIdx.x;
    int im_g = tid & 15, oc_g = tid >> 4;

    u64 acc2[4][2];
    #pragma unroll
    for (int m = 0; m < 4; m++) { acc2[m][0] = 0ull; acc2[m][1] = 0ull; }

    for (int k0 = 0; k0 < 1024; k0 += 32) {
        __syncthreads();
        #pragma unroll
        for (int r = 0; r < 2; r++) {
            int idx = tid + 256 * r;
            int im = idx & 63, kq = idx >> 6;
            float4 v = *(const float4*)&g_c3o[(size_t)(i0 + im) * 1024 + k0 + kq * 4];
            Xs[kq * 4 + 0][im] = v.x;
            Xs[kq * 4 + 1][im] = v.y;
            Xs[kq * 4 + 2][im] = v.z;
            Xs[kq * 4 + 3][im] = v.w;
        }
        #pragma unroll
        for (int r = 0; r < 2; r++) {
            int idx = tid + 256 * r;
            int kk = idx >> 4, oc4 = idx & 15;
            float4 v = *(const float4*)&g_fcwt[(size_t)(k0 + kk) * 512 + j0 + oc4 * 4];
            *(float4*)&Ws[kk][oc4 * 4] = v;
        }
        __syncthreads();
        #pragma unroll
        for (int kk = 0; kk < 32; kk++) {
            float4 wv = *(const float4*)&Ws[kk][oc_g * 4];
            float4 xv = *(const float4*)&Xs[kk][im_g * 4];
            u64 wp0 = pack2(wv.x, wv.y);
            u64 wp1 = pack2(wv.z, wv.w);
            u64 x0 = pack2(xv.x, xv.x);
            u64 x1 = pack2(xv.y, xv.y);
            u64 x2 = pack2(xv.z, xv.z);
            u64 x3 = pack2(xv.w, xv.w);
            acc2[0][0] = fma2(x0, wp0, acc2[0][0]);
            acc2[0][1] = fma2(x0, wp1, acc2[0][1]);
            acc2[1][0] = fma2(x1, wp0, acc2[1][0]);
            acc2[1][1] = fma2(x1, wp1, acc2[1][1]);
            acc2[2][0] = fma2(x2, wp0, acc2[2][0]);
            acc2[2][1] = fma2(x2, wp1, acc2[2][1]);
            acc2[3][0] = fma2(x3, wp0, acc2[3][0]);
            acc2[3][1] = fma2(x3, wp1, acc2[3][1]);
        }
    }
    #pragma unroll
    for (int m = 0; m < 4; m++) {
        int img = i0 + im_g * 4 + m;
        float a0, a1, a2, a3;
        unpack2(acc2[m][0], a0, a1);
        unpack2(acc2[m][1], a2, a3);
        int oc = j0 + oc_g * 4;
        g_h[(size_t)img * MAP + oc + 0] = fmaxf(a0 + bias[oc + 0], 0.f);
        g_h[(size_t)img * MAP + oc + 1] = fmaxf(a1 + bias[oc + 1], 0.f);
        g_h[(size_t)img * MAP + oc + 2] = fmaxf(a2 + bias[oc + 2], 0.f);
        g_h[(size_t)img * MAP + oc + 3] = fmaxf(a3 + bias[oc + 3], 0.f);
    }
}

// ---------------- onehot tail of g_h ----------------
__global__ void k_onehot(const int* __restrict__ lastact) {
    int i = blockIdx.x * 256 + threadIdx.x;
    if (i < TB * NACT) {
        int ib = i / NACT, a = i % NACT;
        g_h[(size_t)ib * MAP + 512 + a] = (lastact[ib] == a) ? 1.f : 0.f;
    }
}

// ---------------- zero acc0 ----------------
__global__ void k_zero() { g_acc0[blockIdx.x * 128 + threadIdx.x] = 0.f; }

// ======== acc0[j][b] = sum_f W[j][f]*s0[b][f] ========
__global__ __launch_bounds__(256) void k_acc0(const float* __restrict__ pol,
                                              const float* __restrict__ val,
                                              const float* __restrict__ s0) {
    __shared__ __align__(16) float Wt2[64][132];
    __shared__ __align__(16) float Ss[64][36];
    int kb0 = blockIdx.x * 256;
    int tid = threadIdx.x;
    int jg = tid >> 3;
    int bg = tid & 7;

    float acc[4][4];
    #pragma unroll
    for (int m = 0; m < 4; m++)
        #pragma unroll
        for (int n = 0; n < 4; n++) acc[m][n] = 0.f;

    for (int sub = 0; sub < 4; sub++) {
        int kbase = kb0 + sub * 64;
        __syncthreads();
        for (int i = tid; i < 8192; i += 256) {
            int kk = i & 63, j = i >> 6;
            const float* src = (j < 64) ? (pol + (size_t)j * FLAT)
                                        : (val + (size_t)(j - 64) * FLAT);
            Wt2[kk][j] = src[kbase + kk];
        }
        for (int i = tid; i < 2048; i += 256) {
            int kk = i & 63, b = i >> 6;
            Ss[kk][b] = s0[(size_t)b * FLAT + kbase + kk];
        }
        __syncthreads();
        #pragma unroll
        for (int kk = 0; kk < 64; kk++) {
            float4 wv = *(const float4*)&Wt2[kk][jg * 4];
            float4 sv = *(const float4*)&Ss[kk][bg * 4];
            acc[0][0] += wv.x * sv.x; acc[0][1] += wv.x * sv.y;
            acc[0][2] += wv.x * sv.z; acc[0][3] += wv.x * sv.w;
            acc[1][0] += wv.y * sv.x; acc[1][1] += wv.y * sv.y;
            acc[1][2] += wv.y * sv.z; acc[1][3] += wv.y * sv.w;
            acc[2][0] += wv.z * sv.x; acc[2][1] += wv.z * sv.y;
            acc[2][2] += wv.z * sv.z; acc[2][3] += wv.z * sv.w;
            acc[3][0] += wv.w * sv.x; acc[3][1] += wv.w * sv.y;
            acc[3][2] += wv.w * sv.z; acc[3][3] += wv.w * sv.w;
        }
    }
    #pragma unroll
    for (int m = 0; m < 4; m++)
        #pragma unroll
        for (int n = 0; n < 4; n++)
            atomicAdd(&g_acc0[(bg * 4 + n) * 128 + jg * 4 + m], acc[m][n]);
}

// ======== pass 1: last-writer scan, one block per env, prefetched =========
__global__ __launch_bounds__(32) void k_codes(const int* __restrict__ pos,
                                              const float* __restrict__ done) {
    __shared__ int lw[256];
    __shared__ int cells[T_];
    __shared__ float dns[T_];
    int b = blockIdx.x;
    int tid = threadIdx.x;
    {
        int r = tid * B_ + b;
        dns[tid] = done[r];
        cells[tid] = pos[r * 2] * 16 + pos[r * 2 + 1];
    }
    for (int c = tid; c < 256; c += 32) lw[c] = -2;
    __syncwarp();
    for (int t = 0; t < T_; t++) {
        if (dns[t] != 0.0f) {
            for (int c = tid; c < 256; c += 32) lw[c] = -1;
            __syncwarp();
        }
        if (tid == 0) {
            int r = t * B_ + b;
            int cell = cells[t];
            g_cell[r] = cell;
            g_code[r] = lw[cell];
            lw[cell] = t;
        }
        __syncwarp();
    }
    for (int c = tid; c < 256; c += 32) g_lastw[b * 256 + c] = lw[c];
}

// ======== pass 2: parallel per-(t,b) contribution dot products ========
__global__ __launch_bounds__(256) void k_dots(const float* __restrict__ s0) {
    __shared__ float delta[520];
    __shared__ float psum[8 * 128];
    int r = blockIdx.x;
    int b = r & 31;
    int tid = threadIdx.x;
    int cell = g_cell[r];
    int code = g_code[r];
    const float* hrow = g_h + (size_t)r * MAP;
    for (int k = tid; k < MAP; k += 256) {
        float old = 0.f;
        if (code >= 0)       old = g_h[(size_t)(code * B_ + b) * MAP + k];
        else if (code == -2) old = s0[(size_t)b * FLAT + k * 256 + cell];
        delta[k] = hrow[k] - old;
    }
    __syncthreads();
    int j4 = tid & 31;
    int kq = tid >> 5;
    const float* wb = g_Wt + (size_t)cell * WCELL + j4 * 4;
    float4 a = make_float4(0.f, 0.f, 0.f, 0.f);
    for (int k = kq; k < MAP; k += 8) {
        float4 w = *(const float4*)(wb + k * 128);
        float d = delta[k];
        a.x += w.x * d; a.y += w.y * d; a.z += w.z * d; a.w += w.w * d;
    }
    psum[kq * 128 + j4 * 4 + 0] = a.x;
    psum[kq * 128 + j4 * 4 + 1] = a.y;
    psum[kq * 128 + j4 * 4 + 2] = a.z;
    psum[kq * 128 + j4 * 4 + 3] = a.w;
    __syncthreads();
    if (tid < 128) {
        float s = 0.f;
        #pragma unroll
        for (int q = 0; q < 8; q++) s += psum[q * 128 + tid];
        g_c[(size_t)r * 128 + tid] = s;
    }
}

// ======== pass 3a: prefix accumulate + tanh (no syncs, fully per-thread) ========
__global__ __launch_bounds__(128) void k_scanfin(const float* __restrict__ done,
                                                 const float* __restrict__ pb1,
                                                 const float* __restrict__ vb1) {
    int b = blockIdx.x;
    int tid = threadIdx.x;
    float accv = g_acc0[b * 128 + tid];
    float bb = (tid < 64) ? pb1[tid] : vb1[tid - 64];
    #pragma unroll 4
    for (int t = 0; t < T_; t++) {
        int r = t * B_ + b;
        float dn = done[r];
        if (dn != 0.0f) accv = 0.f;
        accv += g_c[(size_t)r * 128 + tid];
        g_th[(size_t)r * 128 + tid] = tanhf(accv + bb);
    }
}

// ======== pass 3b: fully parallel head GEMVs (one warp per (t,b) row) ========
__global__ __launch_bounds__(128) void k_heads(const float* __restrict__ pw2,
                                               const float* __restrict__ pb2,
                                               const float* __restrict__ vw2,
                                               const float* __restrict__ vb2,
                                               float* __restrict__ logits,
                                               float* __restrict__ vout) {
    int r = blockIdx.x * 4 + (threadIdx.x >> 5);
    int lane = threadIdx.x & 31;
    const float* th = g_th + (size_t)r * 128;
    float t0 = th[lane], t1 = th[lane + 32];
    float u0 = th[64 + lane], u1 = th[96 + lane];
    #pragma unroll
    for (int a = 0; a < NACT; a++) {
        float p = t0 * pw2[a * 64 + lane] + t1 * pw2[a * 64 + lane + 32];
        #pragma unroll
        for (int s = 16; s > 0; s >>= 1)
            p += __shfl_xor_sync(0xffffffffu, p, s);
        if (lane == 0) logits[r * NACT + a] = p + pb2[a];
    }
    float v = u0 * vw2[lane] + u1 * vw2[lane + 32];
    #pragma unroll
    for (int s = 16; s > 0; s >>= 1)
        v += __shfl_xor_sync(0xffffffffu, v, s);
    if (lane == 0) vout[r] = v + vb2[0];
}

// ---------------- reconstruct final_state ----------------
__global__ __launch_bounds__(256) void k_final(const float* __restrict__ s0,
                                               float* __restrict__ out) {
    int b = blockIdx.y;
    int f = blockIdx.x * 256 + threadIdx.x;
    int cell = f & 255, k = f >> 8;
    int code = g_lastw[b * 256 + cell];
    float v;
    if (code >= 0)       v = g_h[(size_t)(code * B_ + b) * MAP + k];
    else if (code == -2) v = s0[(size_t)b * FLAT + f];
    else                 v = 0.f;
    out[(size_t)b * FLAT + f] = v;
}

// ---------------- host ----------------
extern "C" void kernel_launch(void* const* d_in, const int* in_sizes, int n_in,
                              void* d_out, int out_size) {
    const float* image  = (const float*)d_in[0];
    const int*   lact   = (const int*)  d_in[1];
    const int*   pos    = (const int*)  d_in[2];
    const float* done   = (const float*)d_in[3];
    const float* state0 = (const float*)d_in[4];
    const float* c1w = (const float*)d_in[5];
    const float* c1b = (const float*)d_in[6];
    const float* c2w = (const float*)d_in[7];
    const float* c2b = (const float*)d_in[8];
    const float* c3w = (const float*)d_in[9];
    const float* c3b = (const float*)d_in[10];
    const float* fcw = (const float*)d_in[11];
    const float* fcb = (const float*)d_in[12];
    const float* pw1 = (const float*)d_in[13];
    const float* pb1 = (const float*)d_in[14];
    const float* pw2 = (const float*)d_in[15];
    const float* pb2 = (const float*)d_in[16];
    const float* vw1 = (const float*)d_in[17];
    const float* vb1 = (const float*)d_in[18];
    const float* vw2 = (const float*)d_in[19];
    const float* vb2 = (const float*)d_in[20];

    float* out_logits = (float*)d_out;
    float* out_v      = (float*)d_out + TB * NACT;
    float* out_state  = (float*)d_out + TB * NACT + TB;

    static cudaStream_t sA = nullptr, sB = nullptr;
    static cudaEvent_t ev0, evA, evB, evH, evFin;
    static int init_done = 0;
    if (!init_done) {
        cudaStreamCreateWithFlags(&sA, cudaStreamNonBlocking);
        cudaStreamCreateWithFlags(&sB, cudaStreamNonBlocking);
        cudaEventCreateWithFlags(&ev0,  cudaEventDisableTiming);
        cudaEventCreateWithFlags(&evA,  cudaEventDisableTiming);
        cudaEventCreateWithFlags(&evB,  cudaEventDisableTiming);
        cudaEventCreateWithFlags(&evH,  cudaEventDisableTiming);
        cudaEventCreateWithFlags(&evFin, cudaEventDisableTiming);
        cudaFuncSetAttribute(k_conv1, cudaFuncAttributeMaxDynamicSharedMemorySize, 73856);
        cudaFuncSetAttribute(k_conv2, cudaFuncAttributeMaxDynamicSharedMemorySize, 63744);
        cudaFuncSetAttribute(k_conv3, cudaFuncAttributeMaxDynamicSharedMemorySize, 49408);
        init_done = 1;
    }

    // fork side streams off the capture (default) stream (R7 schedule)
    cudaEventRecord(ev0, 0);
    cudaStreamWaitEvent(sA, ev0, 0);
    cudaStreamWaitEvent(sB, ev0, 0);

    // stream A: codes + zero + acc0 + onehot (independent of conv path)
    k_codes<<<B_, 32, 0, sA>>>(pos, done);
    k_zero <<<32, 128, 0, sA>>>();
    k_acc0 <<<517, 256, 0, sA>>>(pw1, vw1, state0);
    k_onehot<<<(TB * NACT + 255) / 256, 256, 0, sA>>>(lact);
    cudaEventRecord(evA, sA);

    // stream B: big weight transpose + fc transpose
    k_transW2<<<FLAT / 32, 256, 0, sB>>>(pw1, vw1);
    k_transFC<<<dim3(32, 16), dim3(32, 32), 0, sB>>>(fcw);
    cudaEventRecord(evB, sB);

    // main stream: CNN feature path (R5 bodies)
    k_conv1<<<TB, 384, 73856>>>(image, c1w, c1b);
    k_conv2<<<TB / 4, 384, 63744>>>(c2w, c2b);
    k_conv3<<<TB / 4, 256, 49408>>>(c3w, c3b);

    // fc needs transFC
    cudaStreamWaitEvent(0, evB, 0);
    k_fc2<<<dim3(16, 8), 256>>>(fcb);
    cudaEventRecord(evH, 0);

    // final_state on stream B (overlaps dots/scanfin)
    cudaStreamWaitEvent(sB, evH, 0);
    cudaStreamWaitEvent(sB, evA, 0);
    k_final<<<dim3(FLAT / 256, B_), 256, 0, sB>>>(state0, out_state);
    cudaEventRecord(evFin, sB);

    // main stream: dots + prefix + parallel heads
    cudaStreamWaitEvent(0, evA, 0);
    k_dots   <<<TB, 256>>>(state0);
    k_scanfin<<<B_, 128>>>(done, pb1, vb1);
    k_heads  <<<TB / 4, 128>>>(pw2, pb2, vw2, vb2, out_logits, out_v);

    // join stream B back before capture end
    cudaStreamWaitEvent(0, evFin, 0);

    (void)in_sizes; (void)n_in; (void)out_size;
}